// round 8
// baseline (speedup 1.0000x reference)
#include <cuda_runtime.h>
#include <math.h>

#define Nn 512
#define CS 1024
#define CZ 128
#define Hh 12
#define HD 16
#define PQ 4
#define PV 8
#define CATD 2112   // 192 + 96*4 + 1536
#define NN (Nn*Nn)
#define PROJD 1152  // 192 + 384 + 144 + 432
#define QS 0.14433756729740643f   // sqrt(1/48)

typedef unsigned long long ull;

// ---------------- scratch (device globals; no allocation) ----------------
__device__ float g_proj[Nn*PROJD];
__device__ float g_qpts[Nn*Hh*PQ*3];      // [n][h][p][c]
__device__ float g_kT[Hh*HD*Nn];          // [h][d][j]
__device__ float g_vT[Hh*HD*Nn];          // [h][d][j]
__device__ float g_kptsT[Hh*12*Nn];       // [h][p*3+c][j]
__device__ float g_vptsT[Hh*24*Nn];       // [h][p*3+c][j]
__device__ float g_knorm[Hh*Nn];          // [h][j] = sum kp^2
__device__ float g_bias[Hh*NN];           // [h][i][j], pre-scaled by sqrt(1/3)
__device__ float g_att[Hh*NN];
__device__ float g_opt[Nn*Hh*PV*3];
__device__ float g_cat[Nn*CATD];

// ---------------- f32x2 packed helpers ------------------------------------
__device__ __forceinline__ ull pk2(float x, float y) {
    ull r; asm("mov.b64 %0, {%1,%2};" : "=l"(r) : "f"(x), "f"(y)); return r;
}
__device__ __forceinline__ ull dup2(float x) {
    ull r; asm("mov.b64 %0, {%1,%1};" : "=l"(r) : "f"(x)); return r;
}
#define FMA2(c, a, b) asm("fma.rn.f32x2 %0, %1, %2, %0;" : "+l"(c) : "l"(a), "l"(b))
__device__ __forceinline__ void unpk2(ull v, float& lo, float& hi) {
    asm("mov.b64 {%0,%1}, %2;" : "=f"(lo), "=f"(hi) : "l"(v));
}
__device__ __forceinline__ float hadd2(ull v) {
    float lo, hi; unpk2(v, lo, hi); return lo + hi;
}

// ---------------- GEMM: BM=64,BN=64,BK=16, 128 thr, 8x4 micro, f32x2 ------
template<bool PROJ>
__global__ void __launch_bounds__(128)
gemm_kernel(const float* __restrict__ A,
            const float* __restrict__ W0,  const float* __restrict__ b0,
            const float* __restrict__ Wkv, const float* __restrict__ bkv,
            const float* __restrict__ Wqp, const float* __restrict__ bqp,
            const float* __restrict__ Wkvp,const float* __restrict__ bkvp,
            float* __restrict__ C, int Nd, int K) {
    __shared__ __align__(16) ull As2[16][64];   // [k][row] dup pairs
    __shared__ __align__(16) ull Bs2[16][32];   // [k][colpair]
    int tid = threadIdx.x;
    int m0 = blockIdx.y * 64, n0 = blockIdx.x * 64;
    int tx = tid & 15, ty = tid >> 4;

    // A loader: 2 float4 per thread
    int arow = tid >> 1, akb = (tid & 1) * 8;
    const float* Aptr = A + (size_t)(m0 + arow) * K + akb;
    // B loader: 8 consecutive cols per thread (segment-safe: 192/576/720 all %8==0)
    int brow = tid >> 3, bcol8 = (tid & 7) * 8;
    int lcolB = n0 + bcol8;
    const float* Bsrc; int ldw; int lcB;
    if (PROJ) {
        if      (lcolB < 192) { Bsrc = W0;   ldw = 192; lcB = lcolB;       }
        else if (lcolB < 576) { Bsrc = Wkv;  ldw = 384; lcB = lcolB - 192; }
        else if (lcolB < 720) { Bsrc = Wqp;  ldw = 144; lcB = lcolB - 576; }
        else                  { Bsrc = Wkvp; ldw = 432; lcB = lcolB - 720; }
    } else { Bsrc = W0; ldw = Nd; lcB = lcolB; }
    const float* Bptr = Bsrc + (size_t)brow * ldw + lcB;

    float4 a4[2], b4[2];
    a4[0] = *(const float4*)Aptr;      a4[1] = *(const float4*)(Aptr + 4);
    b4[0] = *(const float4*)Bptr;      b4[1] = *(const float4*)(Bptr + 4);

    ull acc[8][2];
    #pragma unroll
    for (int r = 0; r < 8; r++) { acc[r][0] = 0ull; acc[r][1] = 0ull; }

    int KT = K >> 4;
    for (int kt = 0; kt < KT; kt++) {
        __syncthreads();
        As2[akb + 0][arow] = dup2(a4[0].x);
        As2[akb + 1][arow] = dup2(a4[0].y);
        As2[akb + 2][arow] = dup2(a4[0].z);
        As2[akb + 3][arow] = dup2(a4[0].w);
        As2[akb + 4][arow] = dup2(a4[1].x);
        As2[akb + 5][arow] = dup2(a4[1].y);
        As2[akb + 6][arow] = dup2(a4[1].z);
        As2[akb + 7][arow] = dup2(a4[1].w);
        Bs2[brow][(bcol8 >> 1) + 0] = pk2(b4[0].x, b4[0].y);
        Bs2[brow][(bcol8 >> 1) + 1] = pk2(b4[0].z, b4[0].w);
        Bs2[brow][(bcol8 >> 1) + 2] = pk2(b4[1].x, b4[1].y);
        Bs2[brow][(bcol8 >> 1) + 3] = pk2(b4[1].z, b4[1].w);
        __syncthreads();
        if (kt + 1 < KT) {
            const float* An = Aptr + (kt + 1) * 16;
            a4[0] = *(const float4*)An; a4[1] = *(const float4*)(An + 4);
            const float* Bn = Bptr + (size_t)(kt + 1) * 16 * ldw;
            b4[0] = *(const float4*)Bn; b4[1] = *(const float4*)(Bn + 4);
        }
        #pragma unroll
        for (int kk = 0; kk < 16; kk++) {
            ulonglong2 a01 = *(const ulonglong2*)&As2[kk][ty * 8];
            ulonglong2 a23 = *(const ulonglong2*)&As2[kk][ty * 8 + 2];
            ulonglong2 a45 = *(const ulonglong2*)&As2[kk][ty * 8 + 4];
            ulonglong2 a67 = *(const ulonglong2*)&As2[kk][ty * 8 + 6];
            ulonglong2 bp  = *(const ulonglong2*)&Bs2[kk][tx * 2];
            FMA2(acc[0][0], a01.x, bp.x); FMA2(acc[0][1], a01.x, bp.y);
            FMA2(acc[1][0], a01.y, bp.x); FMA2(acc[1][1], a01.y, bp.y);
            FMA2(acc[2][0], a23.x, bp.x); FMA2(acc[2][1], a23.x, bp.y);
            FMA2(acc[3][0], a23.y, bp.x); FMA2(acc[3][1], a23.y, bp.y);
            FMA2(acc[4][0], a45.x, bp.x); FMA2(acc[4][1], a45.x, bp.y);
            FMA2(acc[5][0], a45.y, bp.x); FMA2(acc[5][1], a45.y, bp.y);
            FMA2(acc[6][0], a67.x, bp.x); FMA2(acc[6][1], a67.x, bp.y);
            FMA2(acc[7][0], a67.y, bp.x); FMA2(acc[7][1], a67.y, bp.y);
        }
    }
    int lcol = n0 + tx * 4;
    const float* bsrc; float scale; int lc;
    if (PROJ) {
        if      (lcol < 192) { bsrc = b0;   scale = QS;  lc = lcol;       }
        else if (lcol < 576) { bsrc = bkv;  scale = 1.f; lc = lcol - 192; }
        else if (lcol < 720) { bsrc = bqp;  scale = 1.f; lc = lcol - 576; }
        else                 { bsrc = bkvp; scale = 1.f; lc = lcol - 720; }
    } else { bsrc = b0; scale = 1.f; lc = lcol; }
    float4 bv = *(const float4*)(bsrc + lc);
    #pragma unroll
    for (int r = 0; r < 8; r++) {
        float o0, o1, o2, o3;
        unpk2(acc[r][0], o0, o1);
        unpk2(acc[r][1], o2, o3);
        float4 o;
        o.x = (o0 + bv.x) * scale; o.y = (o1 + bv.y) * scale;
        o.z = (o2 + bv.z) * scale; o.w = (o3 + bv.w) * scale;
        *(float4*)(C + (size_t)(m0 + ty * 8 + r) * Nd + n0 + tx * 4) = o;
    }
}

// ------------- repack k/v into transposed [h][d][j] layouts ---------------
__global__ void repack_kv_kernel() {
    int n = blockIdx.x;
    int tid = threadIdx.x;   // 384 = h*32 + d
    float v = g_proj[n * PROJD + 192 + tid];
    int h = tid >> 5, d = tid & 31;
    if (d < 16) g_kT[(h * 16 + d) * Nn + n] = v;
    else        g_vT[(h * 16 + d - 16) * Nn + n] = v;
}

// ------------- point transforms; k/v points transposed + knorm ------------
__global__ void pts_kernel(const float* __restrict__ rot,
                           const float* __restrict__ trans) {
    int n = blockIdx.x;
    __shared__ float R[9], t3[3];
    __shared__ float kn[Hh][PQ];
    int tid = threadIdx.x;   // 192
    if (tid < 9) R[tid] = rot[n * 9 + tid];
    if (tid < 3) t3[tid] = trans[n * 3 + tid];
    __syncthreads();
    if (tid < 48) {
        int idx = tid;
        const float* raw = g_proj + n * PROJD + 576;
        float p0 = raw[idx], p1 = raw[48 + idx], p2 = raw[96 + idx];
        #pragma unroll
        for (int c = 0; c < 3; c++)
            g_qpts[n * 144 + idx * 3 + c] =
                R[c * 3] * p0 + R[c * 3 + 1] * p1 + R[c * 3 + 2] * p2 + t3[c];
    } else {
        int idx = tid - 48;
        const float* raw = g_proj + n * PROJD + 720;
        float p0 = raw[idx], p1 = raw[144 + idx], p2 = raw[288 + idx];
        int h = idx / 12, r = idx - h * 12;
        float o[3];
        #pragma unroll
        for (int c = 0; c < 3; c++)
            o[c] = R[c * 3] * p0 + R[c * 3 + 1] * p1 + R[c * 3 + 2] * p2 + t3[c];
        if (r < PQ) {
            #pragma unroll
            for (int c = 0; c < 3; c++)
                g_kptsT[(h * 12 + r * 3 + c) * Nn + n] = o[c];
            kn[h][r] = o[0] * o[0] + o[1] * o[1] + o[2] * o[2];
        } else {
            int p = r - PQ;
            #pragma unroll
            for (int c = 0; c < 3; c++)
                g_vptsT[(h * 24 + p * 3 + c) * Nn + n] = o[c];
        }
    }
    __syncthreads();
    if (tid < Hh)
        g_knorm[tid * Nn + n] = kn[tid][0] + kn[tid][1] + kn[tid][2] + kn[tid][3];
}

// ---------- bias: f32x2 over channel pairs, quarter-staged z --------------
// NOTE: zs row stride is 34 floats (136 B) — 8-aligned but NOT 16-aligned.
// All wide accesses to zs are therefore 8-byte (ull), never float4.
__global__ void __launch_bounds__(128)
bias_kernel(const float* __restrict__ z,
            const float* __restrict__ Wb,
            const float* __restrict__ bb) {
    int base = blockIdx.x * 128;
    __shared__ __align__(16) float zs[128][34];   // one quarter (32 ch) of 128 rows
    __shared__ __align__(16) ull WbP[64][Hh];     // [c-pair][h]
    int tid = threadIdx.x;
    for (int t = tid; t < 64 * Hh; t += 128) {
        int cp = t / Hh, h = t - cp * Hh;
        WbP[cp][h] = pk2(Wb[(2 * cp) * Hh + h], Wb[(2 * cp + 1) * Hh + h]);
    }
    ull acc2[Hh];
    #pragma unroll
    for (int h = 0; h < Hh; h++) acc2[h] = 0ull;
    #pragma unroll
    for (int q = 0; q < 4; q++) {
        __syncthreads();
        #pragma unroll
        for (int u = 0; u < 8; u++) {
            int t = tid + u * 128;
            int row = t >> 3, cc = (t & 7) * 4;
            float4 v = *(const float4*)&z[(size_t)(base + row) * CZ + q * 32 + cc];
            *(ull*)&zs[row][cc]     = pk2(v.x, v.y);   // 8-byte stores: stride-safe
            *(ull*)&zs[row][cc + 2] = pk2(v.z, v.w);
        }
        __syncthreads();
        #pragma unroll
        for (int cl = 0; cl < 16; cl++) {          // local c-pair
            ull zp = *(const ull*)&zs[tid][cl * 2];
            const ull* wp = &WbP[q * 16 + cl][0];
            #pragma unroll
            for (int h = 0; h < Hh; h++) FMA2(acc2[h], zp, wp[h]);
        }
    }
    int ij = base + tid;
    #pragma unroll
    for (int h = 0; h < Hh; h++)
        g_bias[h * NN + ij] = 0.5773502691896258f * (hadd2(acc2[h]) + bb[h]);
}

// ---------- attention logits + softmax, 8 rows/block, f32x2 dots ----------
__global__ void __launch_bounds__(256)
attn_kernel(const float* __restrict__ head_w,
            const float* __restrict__ mask) {
    int h = blockIdx.x, i0 = blockIdx.y * 8;
    __shared__ __align__(16) float qv[8][16];   // 64 B rows
    __shared__ __align__(16) float qp[8][12];   // 48 B rows (16-mult)
    __shared__ float mi8[8], qn8[8];
    __shared__ float red[8][8];
    __shared__ float s_hw, s_res[8];
    int tid = threadIdx.x, lane = tid & 31, wid = tid >> 5;
    if (tid < 128) {
        int ii = tid >> 4, d = tid & 15;
        qv[ii][d] = g_proj[(i0 + ii) * PROJD + h * 16 + d];
    }
    if (tid < 96) {
        int ii = tid / 12, e = tid - ii * 12;
        qp[ii][e] = g_qpts[(i0 + ii) * 144 + h * 12 + e];
    }
    if (tid < 8) mi8[tid] = mask[i0 + tid];
    if (tid == 0) {
        float w = head_w[h];
        float sp = fmaxf(w, 0.f) + log1pf(__expf(-fabsf(w)));
        s_hw = sp * 0.5f * 0.13608276348795434f;   // 0.5*sqrt(1/54)
    }
    __syncthreads();
    if (tid < 8) {
        float s = 0.f;
        #pragma unroll
        for (int e = 0; e < 12; e++) s += qp[tid][e] * qp[tid][e];
        qn8[tid] = s;
    }
    __syncthreads();
    float hw = s_hw, hw2 = 2.f * s_hw;
    float logit[8][2];
    #pragma unroll
    for (int jj = 0; jj < 2; jj++) {
        int j = tid + jj * 256;
        ull kx2[8], kp2[6];
        #pragma unroll
        for (int d = 0; d < 8; d++)
            kx2[d] = pk2(g_kT[(h * 16 + 2 * d) * Nn + j],
                         g_kT[(h * 16 + 2 * d + 1) * Nn + j]);
        #pragma unroll
        for (int e = 0; e < 6; e++)
            kp2[e] = pk2(g_kptsT[(h * 12 + 2 * e) * Nn + j],
                         g_kptsT[(h * 12 + 2 * e + 1) * Nn + j]);
        float kn = g_knorm[h * Nn + j];
        float mj = mask[j];
        #pragma unroll
        for (int ii = 0; ii < 8; ii++) {
            ull dk = 0ull, dp = 0ull;
            const ull* q2 = (const ull*)&qv[ii][0];
            const ull* p2 = (const ull*)&qp[ii][0];
            #pragma unroll
            for (int d = 0; d < 8; d++) FMA2(dk, q2[d], kx2[d]);
            #pragma unroll
            for (int e = 0; e < 6; e++) FMA2(dp, p2[e], kp2[e]);
            float dot = hadd2(dk), dpt = hadd2(dp);
            logit[ii][jj] = dot + g_bias[(h << 18) + ((i0 + ii) << 9) + j]
                          - hw * (qn8[ii] + kn) + hw2 * dpt
                          + 100000.0f * (mi8[ii] * mj - 1.0f);
        }
    }
    #pragma unroll
    for (int ii = 0; ii < 8; ii++) {
        float m = fmaxf(logit[ii][0], logit[ii][1]);
        #pragma unroll
        for (int o = 16; o > 0; o >>= 1) m = fmaxf(m, __shfl_xor_sync(0xffffffffu, m, o));
        if (lane == 0) red[ii][wid] = m;
    }
    __syncthreads();
    if (tid < 8) {
        float mm = red[tid][0];
        #pragma unroll
        for (int w = 1; w < 8; w++) mm = fmaxf(mm, red[tid][w]);
        s_res[tid] = mm;
    }
    __syncthreads();
    #pragma unroll
    for (int ii = 0; ii < 8; ii++) {
        float m = s_res[ii];
        logit[ii][0] = __expf(logit[ii][0] - m);
        logit[ii][1] = __expf(logit[ii][1] - m);
        float ss = logit[ii][0] + logit[ii][1];
        #pragma unroll
        for (int o = 16; o > 0; o >>= 1) ss += __shfl_xor_sync(0xffffffffu, ss, o);
        if (lane == 0) red[ii][wid] = ss;
    }
    __syncthreads();
    if (tid < 8) {
        float t = 0.f;
        #pragma unroll
        for (int w = 0; w < 8; w++) t += red[tid][w];
        s_res[tid] = 1.f / t;
    }
    __syncthreads();
    #pragma unroll
    for (int ii = 0; ii < 8; ii++) {
        float inv = s_res[ii];
        int o = (h << 18) + ((i0 + ii) << 9);
        g_att[o + tid]       = logit[ii][0] * inv;
        g_att[o + tid + 256] = logit[ii][1] * inv;
    }
}

// ---------- a@[v | v_pts] per head, 32-row tiles, coalesced loads ---------
__global__ void __launch_bounds__(320)
av_kernel() {
    int h = blockIdx.x;
    int i0 = blockIdx.y * 32;
    __shared__ __align__(16) float As[32][36];
    __shared__ __align__(16) float Vt[32][40];
    int tid = threadIdx.x;
    int tx = tid % 40, ty = tid / 40;
    float acc[4] = {};
    for (int k0 = 0; k0 < Nn; k0 += 32) {
        __syncthreads();
        for (int t = tid; t < 1024; t += 320) {
            int j = t & 31, ii = t >> 5;
            As[j][ii] = g_att[(h << 18) + ((i0 + ii) << 9) + k0 + j];
        }
        for (int t = tid; t < 1280; t += 320) {
            int col = t >> 5, row = t & 31;
            Vt[row][col] = (col < 16)
                ? g_vT[(h * 16 + col) * Nn + k0 + row]
                : g_vptsT[(h * 24 + col - 16) * Nn + k0 + row];
        }
        __syncthreads();
        #pragma unroll
        for (int j = 0; j < 32; j++) {
            float b = Vt[j][tx];
            float4 a = *(const float4*)&As[j][ty * 4];   // rows 144 B (16-mult), ty*4*4 16-mult
            acc[0] += a.x * b; acc[1] += a.y * b;
            acc[2] += a.z * b; acc[3] += a.w * b;
        }
    }
    #pragma unroll
    for (int r = 0; r < 4; r++) {
        int i = i0 + ty * 4 + r;
        if (tx < 16) g_cat[(size_t)i * CATD + h * 16 + tx] = acc[r];
        else         g_opt[i * 288 + h * 24 + (tx - 16)]   = acc[r];
    }
}

// ---------- inverse frame transform + norm -> cat sections ----------------
__global__ void transform_kernel(const float* __restrict__ rot,
                                 const float* __restrict__ trans) {
    int n = blockIdx.x;
    __shared__ float R[9], t3[3];
    int tid = threadIdx.x;   // 128
    if (tid < 9) R[tid] = rot[n * 9 + tid];
    if (tid < 3) t3[tid] = trans[n * 3 + tid];
    __syncthreads();
    if (tid < 96) {
        int h = tid >> 3, p = tid & 7;
        int base = n * 288 + h * 24 + p * 3;
        float x = g_opt[base + 0] - t3[0];
        float y = g_opt[base + 1] - t3[1];
        float z = g_opt[base + 2] - t3[2];
        float lx = R[0] * x + R[3] * y + R[6] * z;
        float ly = R[1] * x + R[4] * y + R[7] * z;
        float lz = R[2] * x + R[5] * y + R[8] * z;
        size_t o = (size_t)n * CATD;
        int idx = h * 8 + p;
        g_cat[o + 192 + idx] = lx;
        g_cat[o + 288 + idx] = ly;
        g_cat[o + 384 + idx] = lz;
        g_cat[o + 480 + idx] = sqrtf(lx * lx + ly * ly + lz * lz + 1e-8f);
    }
}

// ---------- o_pair: f32x2 over j-pairs, 4 j-quarters ----------------------
__global__ void __launch_bounds__(512)
opair_kernel(const float* __restrict__ z) {
    int i = blockIdx.x;
    __shared__ __align__(16) float as[Hh][520];   // rows 2080 B (16-mult)
    int tid = threadIdx.x;
    int c = tid & 127, jq = tid >> 7;
    for (int t = tid; t < Hh * Nn; t += 512) {
        int h = t >> 9, j = t & 511;
        as[h][j] = g_att[(h << 18) + (i << 9) + j];
    }
    __syncthreads();
    ull acc2[Hh];
    #pragma unroll
    for (int h = 0; h < Hh; h++) acc2[h] = 0ull;
    const float* zrow = z + (size_t)i * Nn * CZ + c;
    int j0 = jq * 128;
    for (int j = j0; j < j0 + 128; j += 4) {
        float z0 = zrow[(size_t)(j + 0) * CZ];
        float z1 = zrow[(size_t)(j + 1) * CZ];
        float z2 = zrow[(size_t)(j + 2) * CZ];
        float z3 = zrow[(size_t)(j + 3) * CZ];
        ull zp0 = pk2(z0, z1), zp1 = pk2(z2, z3);
        #pragma unroll
        for (int h = 0; h < Hh; h++) {
            ulonglong2 ap = *(const ulonglong2*)&as[h][j];   // j%4==0 -> 16-aligned
            FMA2(acc2[h], ap.x, zp0);
            FMA2(acc2[h], ap.y, zp1);
        }
    }
    __syncthreads();
    float* red = &as[0][0];
    if (jq > 0) {
        #pragma unroll
        for (int h = 0; h < Hh; h++)
            red[(jq - 1) * 1536 + h * 128 + c] = hadd2(acc2[h]);
    }
    __syncthreads();
    if (jq == 0) {
        size_t o = (size_t)i * CATD + 576;
        #pragma unroll
        for (int h = 0; h < Hh; h++) {
            float v = hadd2(acc2[h]) + red[h * 128 + c] + red[1536 + h * 128 + c]
                             + red[3072 + h * 128 + c];
            g_cat[o + h * CZ + c] = v;
        }
    }
}

// --------------------------------------------------------------------------
extern "C" void kernel_launch(void* const* d_in, const int* in_sizes, int n_in,
                              void* d_out, int out_size) {
    const float* s      = (const float*)d_in[0];
    const float* z      = (const float*)d_in[1];
    const float* rot    = (const float*)d_in[2];
    const float* trans  = (const float*)d_in[3];
    const float* mask   = (const float*)d_in[4];
    const float* Wq     = (const float*)d_in[5];
    const float* bq     = (const float*)d_in[6];
    const float* Wkv    = (const float*)d_in[7];
    const float* bkv    = (const float*)d_in[8];
    const float* Wqp    = (const float*)d_in[9];
    const float* bqp    = (const float*)d_in[10];
    const float* Wkvp   = (const float*)d_in[11];
    const float* bkvp   = (const float*)d_in[12];
    const float* Wb     = (const float*)d_in[13];
    const float* bb     = (const float*)d_in[14];
    const float* head_w = (const float*)d_in[15];
    const float* Wout   = (const float*)d_in[16];
    const float* bout   = (const float*)d_in[17];
    float* out = (float*)d_out;

    float *p_proj, *p_cat;
    cudaGetSymbolAddress((void**)&p_proj, g_proj);
    cudaGetSymbolAddress((void**)&p_cat,  g_cat);

    gemm_kernel<true><<<dim3(PROJD / 64, Nn / 64), 128>>>(
        s, Wq, bq, Wkv, bkv, Wqp, bqp, Wkvp, bkvp, p_proj, PROJD, CS);
    repack_kv_kernel<<<Nn, 384>>>();
    pts_kernel<<<Nn, 192>>>(rot, trans);
    bias_kernel<<<NN / 128, 128>>>(z, Wb, bb);
    attn_kernel<<<dim3(Hh, Nn / 8), 256>>>(head_w, mask);
    av_kernel<<<dim3(Hh, Nn / 32), 320>>>();
    transform_kernel<<<Nn, 128>>>(rot, trans);
    opair_kernel<<<Nn, 512>>>(z);
    gemm_kernel<false><<<dim3(CS / 64, Nn / 64), 128>>>(
        p_cat, Wout, bout, 0, 0, 0, 0, 0, 0, out, CS, CATD);
}

// round 10
// speedup vs baseline: 1.1543x; 1.1543x over previous
#include <cuda_runtime.h>
#include <math.h>

#define Nn 512
#define CS 1024
#define CZ 128
#define Hh 12
#define HD 16
#define PQ 4
#define PV 8
#define CATD 2112   // 192 + 96*4 + 1536
#define NN (Nn*Nn)
#define PROJD 1152  // 192 + 384 + 144 + 432
#define QS 0.14433756729740643f   // sqrt(1/48)

typedef unsigned long long ull;

// ---------------- scratch (device globals; no allocation) ----------------
__device__ float g_proj[Nn*PROJD];
__device__ float g_qpts[Nn*Hh*PQ*3];      // [n][h][p][c]
__device__ float g_kT[Hh*HD*Nn];          // [h][d][j]
__device__ float g_vT[Hh*HD*Nn];          // [h][d][j]
__device__ float g_kptsT[Hh*12*Nn];       // [h][p*3+c][j]
__device__ float g_vptsT[Hh*24*Nn];       // [h][p*3+c][j]
__device__ float g_knorm[Hh*Nn];          // [h][j] = sum kp^2
__device__ float g_bias[Hh*NN];           // [h][i][j], pre-scaled by sqrt(1/3)
__device__ float g_att[Hh*NN];
__device__ float g_opt[Nn*Hh*PV*3];
__device__ float g_cat[Nn*CATD];

// ---------------- f32x2 packed helpers ------------------------------------
__device__ __forceinline__ ull pk2(float x, float y) {
    ull r; asm("mov.b64 %0, {%1,%2};" : "=l"(r) : "f"(x), "f"(y)); return r;
}
__device__ __forceinline__ ull dup2(float x) {
    ull r; asm("mov.b64 %0, {%1,%1};" : "=l"(r) : "f"(x)); return r;
}
#define FMA2(c, a, b) asm("fma.rn.f32x2 %0, %1, %2, %0;" : "+l"(c) : "l"(a), "l"(b))
__device__ __forceinline__ void unpk2(ull v, float& lo, float& hi) {
    asm("mov.b64 {%0,%1}, %2;" : "=f"(lo), "=f"(hi) : "l"(v));
}
__device__ __forceinline__ float hadd2(ull v) {
    float lo, hi; unpk2(v, lo, hi); return lo + hi;
}

// ------- GEMM (R4 known-good): BM=64,BN=64,BK=16, 256 thr, 4x4 f32x2 ------
template<bool PROJ>
__global__ void __launch_bounds__(256)
gemm_kernel(const float* __restrict__ A,
            const float* __restrict__ W0,  const float* __restrict__ b0,
            const float* __restrict__ Wkv, const float* __restrict__ bkv,
            const float* __restrict__ Wqp, const float* __restrict__ bqp,
            const float* __restrict__ Wkvp,const float* __restrict__ bkvp,
            float* __restrict__ C, int Nd, int K) {
    __shared__ __align__(16) ull As2[16][64];   // [k][row] dup pairs {a,a}
    __shared__ __align__(16) ull Bs2[16][32];   // [k][colpair] {b0,b1}
    int tid = threadIdx.x;
    int m0 = blockIdx.y * 64, n0 = blockIdx.x * 64;
    int tx = tid & 15, ty = tid >> 4;

    // A loader: row = tid>>2, k-offset = (tid&3)*4
    int arow = tid >> 2, akb = (tid & 3) * 4;
    const float* Aptr = A + (size_t)(m0 + arow) * K + akb;

    // B loader: col = n0 + tx*4, k-row = ty
    int lcol = n0 + tx * 4;
    const float* Bsrc; int ldw; int lc;
    if (PROJ) {
        if      (lcol < 192) { Bsrc = W0;   ldw = 192; lc = lcol;       }
        else if (lcol < 576) { Bsrc = Wkv;  ldw = 384; lc = lcol - 192; }
        else if (lcol < 720) { Bsrc = Wqp;  ldw = 144; lc = lcol - 576; }
        else                 { Bsrc = Wkvp; ldw = 432; lc = lcol - 720; }
    } else { Bsrc = W0; ldw = Nd; lc = lcol; }
    const float* Bptr = Bsrc + (size_t)ty * ldw + lc;

    float4 a4 = *(const float4*)Aptr;
    float4 b4 = *(const float4*)Bptr;

    ull acc[4][2];
    #pragma unroll
    for (int r = 0; r < 4; r++) { acc[r][0] = 0ull; acc[r][1] = 0ull; }

    int KT = K >> 4;
    for (int kt = 0; kt < KT; kt++) {
        __syncthreads();
        As2[akb + 0][arow] = dup2(a4.x);
        As2[akb + 1][arow] = dup2(a4.y);
        As2[akb + 2][arow] = dup2(a4.z);
        As2[akb + 3][arow] = dup2(a4.w);
        Bs2[ty][tx * 2]     = pk2(b4.x, b4.y);
        Bs2[ty][tx * 2 + 1] = pk2(b4.z, b4.w);
        __syncthreads();
        if (kt + 1 < KT) {
            a4 = *(const float4*)(Aptr + (kt + 1) * 16);
            b4 = *(const float4*)(Bptr + (size_t)(kt + 1) * 16 * ldw);
        }
        #pragma unroll
        for (int kk = 0; kk < 16; kk++) {
            ulonglong2 ap0 = *(const ulonglong2*)&As2[kk][ty * 4];
            ulonglong2 ap1 = *(const ulonglong2*)&As2[kk][ty * 4 + 2];
            ulonglong2 bp  = *(const ulonglong2*)&Bs2[kk][tx * 2];
            FMA2(acc[0][0], ap0.x, bp.x); FMA2(acc[0][1], ap0.x, bp.y);
            FMA2(acc[1][0], ap0.y, bp.x); FMA2(acc[1][1], ap0.y, bp.y);
            FMA2(acc[2][0], ap1.x, bp.x); FMA2(acc[2][1], ap1.x, bp.y);
            FMA2(acc[3][0], ap1.y, bp.x); FMA2(acc[3][1], ap1.y, bp.y);
        }
    }
    const float* bsrc; float scale;
    if (PROJ) {
        if      (lcol < 192) { bsrc = b0;   scale = QS; }
        else if (lcol < 576) { bsrc = bkv;  scale = 1.f; }
        else if (lcol < 720) { bsrc = bqp;  scale = 1.f; }
        else                 { bsrc = bkvp; scale = 1.f; }
    } else { bsrc = b0; scale = 1.f; }
    int lcb = PROJ ? ((lcol < 192) ? lcol : (lcol < 576) ? lcol - 192
                       : (lcol < 720) ? lcol - 576 : lcol - 720) : lcol;
    float4 bv = *(const float4*)(bsrc + lcb);
    #pragma unroll
    for (int r = 0; r < 4; r++) {
        float o0, o1, o2, o3;
        unpk2(acc[r][0], o0, o1);
        unpk2(acc[r][1], o2, o3);
        float4 o;
        o.x = (o0 + bv.x) * scale; o.y = (o1 + bv.y) * scale;
        o.z = (o2 + bv.z) * scale; o.w = (o3 + bv.w) * scale;
        *(float4*)(C + (size_t)(m0 + ty * 4 + r) * Nd + n0 + tx * 4) = o;
    }
}

// ------------- repack k/v into transposed [h][d][j] layouts ---------------
__global__ void repack_kv_kernel() {
    int n = blockIdx.x;
    int tid = threadIdx.x;   // 384 = h*32 + d
    float v = g_proj[n * PROJD + 192 + tid];
    int h = tid >> 5, d = tid & 31;
    if (d < 16) g_kT[(h * 16 + d) * Nn + n] = v;
    else        g_vT[(h * 16 + d - 16) * Nn + n] = v;
}

// ------------- point transforms; k/v points transposed + knorm ------------
__global__ void pts_kernel(const float* __restrict__ rot,
                           const float* __restrict__ trans) {
    int n = blockIdx.x;
    __shared__ float R[9], t3[3];
    __shared__ float kn[Hh][PQ];
    int tid = threadIdx.x;   // 192
    if (tid < 9) R[tid] = rot[n * 9 + tid];
    if (tid < 3) t3[tid] = trans[n * 3 + tid];
    __syncthreads();
    if (tid < 48) {
        int idx = tid;
        const float* raw = g_proj + n * PROJD + 576;
        float p0 = raw[idx], p1 = raw[48 + idx], p2 = raw[96 + idx];
        #pragma unroll
        for (int c = 0; c < 3; c++)
            g_qpts[n * 144 + idx * 3 + c] =
                R[c * 3] * p0 + R[c * 3 + 1] * p1 + R[c * 3 + 2] * p2 + t3[c];
    } else {
        int idx = tid - 48;
        const float* raw = g_proj + n * PROJD + 720;
        float p0 = raw[idx], p1 = raw[144 + idx], p2 = raw[288 + idx];
        int h = idx / 12, r = idx - h * 12;
        float o[3];
        #pragma unroll
        for (int c = 0; c < 3; c++)
            o[c] = R[c * 3] * p0 + R[c * 3 + 1] * p1 + R[c * 3 + 2] * p2 + t3[c];
        if (r < PQ) {
            #pragma unroll
            for (int c = 0; c < 3; c++)
                g_kptsT[(h * 12 + r * 3 + c) * Nn + n] = o[c];
            kn[h][r] = o[0] * o[0] + o[1] * o[1] + o[2] * o[2];
        } else {
            int p = r - PQ;
            #pragma unroll
            for (int c = 0; c < 3; c++)
                g_vptsT[(h * 24 + p * 3 + c) * Nn + n] = o[c];
        }
    }
    __syncthreads();
    if (tid < Hh)
        g_knorm[tid * Nn + n] = kn[tid][0] + kn[tid][1] + kn[tid][2] + kn[tid][3];
}

// ---------- bias: f32x2, quarter-staged z, vectorized W loads -------------
__global__ void __launch_bounds__(128)
bias_kernel(const float* __restrict__ z,
            const float* __restrict__ Wb,
            const float* __restrict__ bb) {
    int base = blockIdx.x * 128;
    __shared__ __align__(16) float zs[128][34];   // row stride 136 B: 8-aligned only
    __shared__ __align__(16) ull WbP[64][Hh];     // row stride 96 B: 16-aligned
    int tid = threadIdx.x;
    for (int t = tid; t < 64 * Hh; t += 128) {
        int cp = t / Hh, h = t - cp * Hh;
        WbP[cp][h] = pk2(Wb[(2 * cp) * Hh + h], Wb[(2 * cp + 1) * Hh + h]);
    }
    ull acc2[Hh];
    #pragma unroll
    for (int h = 0; h < Hh; h++) acc2[h] = 0ull;
    #pragma unroll
    for (int q = 0; q < 4; q++) {
        __syncthreads();
        #pragma unroll
        for (int u = 0; u < 8; u++) {
            int t = tid + u * 128;
            int row = t >> 3, cc = (t & 7) * 4;
            float4 v = *(const float4*)&z[(size_t)(base + row) * CZ + q * 32 + cc];
            *(ull*)&zs[row][cc]     = pk2(v.x, v.y);   // 8-byte stores: stride-safe
            *(ull*)&zs[row][cc + 2] = pk2(v.z, v.w);
        }
        __syncthreads();
        #pragma unroll
        for (int cl = 0; cl < 16; cl++) {
            ull zp = *(const ull*)&zs[tid][cl * 2];
            const ull* wp = &WbP[q * 16 + cl][0];
            #pragma unroll
            for (int hp = 0; hp < 6; hp++) {       // 2 heads per LDS.128
                ulonglong2 w2 = *(const ulonglong2*)(wp + hp * 2);
                FMA2(acc2[2 * hp],     zp, w2.x);
                FMA2(acc2[2 * hp + 1], zp, w2.y);
            }
        }
    }
    int ij = base + tid;
    #pragma unroll
    for (int h = 0; h < Hh; h++)
        g_bias[h * NN + ij] = 0.5773502691896258f * (hadd2(acc2[h]) + bb[h]);
}

// ---------- attention logits + softmax, 8 rows/block, f32x2 dots ----------
__global__ void __launch_bounds__(256)
attn_kernel(const float* __restrict__ head_w,
            const float* __restrict__ mask) {
    int h = blockIdx.x, i0 = blockIdx.y * 8;
    __shared__ __align__(16) float qv[8][16];
    __shared__ __align__(16) float qp[8][12];
    __shared__ float mi8[8], qn8[8];
    __shared__ float red[8][8];
    __shared__ float s_hw, s_res[8];
    int tid = threadIdx.x, lane = tid & 31, wid = tid >> 5;
    if (tid < 128) {
        int ii = tid >> 4, d = tid & 15;
        qv[ii][d] = g_proj[(i0 + ii) * PROJD + h * 16 + d];
    }
    if (tid < 96) {
        int ii = tid / 12, e = tid - ii * 12;
        qp[ii][e] = g_qpts[(i0 + ii) * 144 + h * 12 + e];
    }
    if (tid < 8) mi8[tid] = mask[i0 + tid];
    if (tid == 0) {
        float w = head_w[h];
        float sp = fmaxf(w, 0.f) + log1pf(__expf(-fabsf(w)));
        s_hw = sp * 0.5f * 0.13608276348795434f;   // 0.5*sqrt(1/54)
    }
    __syncthreads();
    if (tid < 8) {
        float s = 0.f;
        #pragma unroll
        for (int e = 0; e < 12; e++) s += qp[tid][e] * qp[tid][e];
        qn8[tid] = s;
    }
    __syncthreads();
    float hw = s_hw, hw2 = 2.f * s_hw;
    float logit[8][2];
    #pragma unroll
    for (int jj = 0; jj < 2; jj++) {
        int j = tid + jj * 256;
        ull kx2[8], kp2[6];
        #pragma unroll
        for (int d = 0; d < 8; d++)
            kx2[d] = pk2(g_kT[(h * 16 + 2 * d) * Nn + j],
                         g_kT[(h * 16 + 2 * d + 1) * Nn + j]);
        #pragma unroll
        for (int e = 0; e < 6; e++)
            kp2[e] = pk2(g_kptsT[(h * 12 + 2 * e) * Nn + j],
                         g_kptsT[(h * 12 + 2 * e + 1) * Nn + j]);
        float kn = g_knorm[h * Nn + j];
        float mj = mask[j];
        #pragma unroll
        for (int ii = 0; ii < 8; ii++) {
            ull dk = 0ull, dp = 0ull;
            const ull* q2 = (const ull*)&qv[ii][0];
            const ull* p2 = (const ull*)&qp[ii][0];
            #pragma unroll
            for (int d = 0; d < 8; d++) FMA2(dk, q2[d], kx2[d]);
            #pragma unroll
            for (int e = 0; e < 6; e++) FMA2(dp, p2[e], kp2[e]);
            float dot = hadd2(dk), dpt = hadd2(dp);
            logit[ii][jj] = dot + g_bias[(h << 18) + ((i0 + ii) << 9) + j]
                          - hw * (qn8[ii] + kn) + hw2 * dpt
                          + 100000.0f * (mi8[ii] * mj - 1.0f);
        }
    }
    #pragma unroll
    for (int ii = 0; ii < 8; ii++) {
        float m = fmaxf(logit[ii][0], logit[ii][1]);
        #pragma unroll
        for (int o = 16; o > 0; o >>= 1) m = fmaxf(m, __shfl_xor_sync(0xffffffffu, m, o));
        if (lane == 0) red[ii][wid] = m;
    }
    __syncthreads();
    if (tid < 8) {
        float mm = red[tid][0];
        #pragma unroll
        for (int w = 1; w < 8; w++) mm = fmaxf(mm, red[tid][w]);
        s_res[tid] = mm;
    }
    __syncthreads();
    #pragma unroll
    for (int ii = 0; ii < 8; ii++) {
        float m = s_res[ii];
        logit[ii][0] = __expf(logit[ii][0] - m);
        logit[ii][1] = __expf(logit[ii][1] - m);
        float ss = logit[ii][0] + logit[ii][1];
        #pragma unroll
        for (int o = 16; o > 0; o >>= 1) ss += __shfl_xor_sync(0xffffffffu, ss, o);
        if (lane == 0) red[ii][wid] = ss;
    }
    __syncthreads();
    if (tid < 8) {
        float t = 0.f;
        #pragma unroll
        for (int w = 0; w < 8; w++) t += red[tid][w];
        s_res[tid] = 1.f / t;
    }
    __syncthreads();
    #pragma unroll
    for (int ii = 0; ii < 8; ii++) {
        float inv = s_res[ii];
        int o = (h << 18) + ((i0 + ii) << 9);
        g_att[o + tid]       = logit[ii][0] * inv;
        g_att[o + tid + 256] = logit[ii][1] * inv;
    }
}

// ---------- a@[v | v_pts] per head, 32-row tiles, coalesced loads ---------
__global__ void __launch_bounds__(320)
av_kernel() {
    int h = blockIdx.x;
    int i0 = blockIdx.y * 32;
    __shared__ __align__(16) float As[32][36];
    __shared__ __align__(16) float Vt[32][40];
    int tid = threadIdx.x;
    int tx = tid % 40, ty = tid / 40;
    float acc[4] = {};
    for (int k0 = 0; k0 < Nn; k0 += 32) {
        __syncthreads();
        for (int t = tid; t < 1024; t += 320) {
            int j = t & 31, ii = t >> 5;
            As[j][ii] = g_att[(h << 18) + ((i0 + ii) << 9) + k0 + j];
        }
        for (int t = tid; t < 1280; t += 320) {
            int col = t >> 5, row = t & 31;
            Vt[row][col] = (col < 16)
                ? g_vT[(h * 16 + col) * Nn + k0 + row]
                : g_vptsT[(h * 24 + col - 16) * Nn + k0 + row];
        }
        __syncthreads();
        #pragma unroll
        for (int j = 0; j < 32; j++) {
            float b = Vt[j][tx];
            float4 a = *(const float4*)&As[j][ty * 4];
            acc[0] += a.x * b; acc[1] += a.y * b;
            acc[2] += a.z * b; acc[3] += a.w * b;
        }
    }
    #pragma unroll
    for (int r = 0; r < 4; r++) {
        int i = i0 + ty * 4 + r;
        if (tx < 16) g_cat[(size_t)i * CATD + h * 16 + tx] = acc[r];
        else         g_opt[i * 288 + h * 24 + (tx - 16)]   = acc[r];
    }
}

// ---------- inverse frame transform + norm -> cat sections ----------------
__global__ void transform_kernel(const float* __restrict__ rot,
                                 const float* __restrict__ trans) {
    int n = blockIdx.x;
    __shared__ float R[9], t3[3];
    int tid = threadIdx.x;   // 128
    if (tid < 9) R[tid] = rot[n * 9 + tid];
    if (tid < 3) t3[tid] = trans[n * 3 + tid];
    __syncthreads();
    if (tid < 96) {
        int h = tid >> 3, p = tid & 7;
        int base = n * 288 + h * 24 + p * 3;
        float x = g_opt[base + 0] - t3[0];
        float y = g_opt[base + 1] - t3[1];
        float z = g_opt[base + 2] - t3[2];
        float lx = R[0] * x + R[3] * y + R[6] * z;
        float ly = R[1] * x + R[4] * y + R[7] * z;
        float lz = R[2] * x + R[5] * y + R[8] * z;
        size_t o = (size_t)n * CATD;
        int idx = h * 8 + p;
        g_cat[o + 192 + idx] = lx;
        g_cat[o + 288 + idx] = ly;
        g_cat[o + 384 + idx] = lz;
        g_cat[o + 480 + idx] = sqrtf(lx * lx + ly * ly + lz * lz + 1e-8f);
    }
}

// ---------- o_pair: f32x2 over j-pairs, 4 j-quarters ----------------------
__global__ void __launch_bounds__(512)
opair_kernel(const float* __restrict__ z) {
    int i = blockIdx.x;
    __shared__ __align__(16) float as[Hh][520];
    int tid = threadIdx.x;
    int c = tid & 127, jq = tid >> 7;
    for (int t = tid; t < Hh * Nn; t += 512) {
        int h = t >> 9, j = t & 511;
        as[h][j] = g_att[(h << 18) + (i << 9) + j];
    }
    __syncthreads();
    ull acc2[Hh];
    #pragma unroll
    for (int h = 0; h < Hh; h++) acc2[h] = 0ull;
    const float* zrow = z + (size_t)i * Nn * CZ + c;
    int j0 = jq * 128;
    for (int j = j0; j < j0 + 128; j += 4) {
        float z0 = zrow[(size_t)(j + 0) * CZ];
        float z1 = zrow[(size_t)(j + 1) * CZ];
        float z2 = zrow[(size_t)(j + 2) * CZ];
        float z3 = zrow[(size_t)(j + 3) * CZ];
        ull zp0 = pk2(z0, z1), zp1 = pk2(z2, z3);
        #pragma unroll
        for (int h = 0; h < Hh; h++) {
            ulonglong2 ap = *(const ulonglong2*)&as[h][j];
            FMA2(acc2[h], ap.x, zp0);
            FMA2(acc2[h], ap.y, zp1);
        }
    }
    __syncthreads();
    float* red = &as[0][0];
    if (jq > 0) {
        #pragma unroll
        for (int h = 0; h < Hh; h++)
            red[(jq - 1) * 1536 + h * 128 + c] = hadd2(acc2[h]);
    }
    __syncthreads();
    if (jq == 0) {
        size_t o = (size_t)i * CATD + 576;
        #pragma unroll
        for (int h = 0; h < Hh; h++) {
            float v = hadd2(acc2[h]) + red[h * 128 + c] + red[1536 + h * 128 + c]
                             + red[3072 + h * 128 + c];
            g_cat[o + h * CZ + c] = v;
        }
    }
}

// --------------------------------------------------------------------------
extern "C" void kernel_launch(void* const* d_in, const int* in_sizes, int n_in,
                              void* d_out, int out_size) {
    const float* s      = (const float*)d_in[0];
    const float* z      = (const float*)d_in[1];
    const float* rot    = (const float*)d_in[2];
    const float* trans  = (const float*)d_in[3];
    const float* mask   = (const float*)d_in[4];
    const float* Wq     = (const float*)d_in[5];
    const float* bq     = (const float*)d_in[6];
    const float* Wkv    = (const float*)d_in[7];
    const float* bkv    = (const float*)d_in[8];
    const float* Wqp    = (const float*)d_in[9];
    const float* bqp    = (const float*)d_in[10];
    const float* Wkvp   = (const float*)d_in[11];
    const float* bkvp   = (const float*)d_in[12];
    const float* Wb     = (const float*)d_in[13];
    const float* bb     = (const float*)d_in[14];
    const float* head_w = (const float*)d_in[15];
    const float* Wout   = (const float*)d_in[16];
    const float* bout   = (const float*)d_in[17];
    float* out = (float*)d_out;

    float *p_proj, *p_cat;
    cudaGetSymbolAddress((void**)&p_proj, g_proj);
    cudaGetSymbolAddress((void**)&p_cat,  g_cat);

    gemm_kernel<true><<<dim3(PROJD / 64, Nn / 64), 256>>>(
        s, Wq, bq, Wkv, bkv, Wqp, bqp, Wkvp, bkvp, p_proj, PROJD, CS);
    repack_kv_kernel<<<Nn, 384>>>();
    pts_kernel<<<Nn, 192>>>(rot, trans);
    bias_kernel<<<NN / 128, 128>>>(z, Wb, bb);
    attn_kernel<<<dim3(Hh, Nn / 8), 256>>>(head_w, mask);
    av_kernel<<<dim3(Hh, Nn / 32), 320>>>();
    transform_kernel<<<Nn, 128>>>(rot, trans);
    opair_kernel<<<Nn, 512>>>(z);
    gemm_kernel<false><<<dim3(CS / 64, Nn / 64), 256>>>(
        p_cat, Wout, bout, 0, 0, 0, 0, 0, 0, out, CS, CATD);
}

// round 11
// speedup vs baseline: 1.1679x; 1.0118x over previous
#include <cuda_runtime.h>
#include <math.h>

#define Nn 512
#define CS 1024
#define CZ 128
#define Hh 12
#define HD 16
#define PQ 4
#define PV 8
#define CATD 2112   // 192 + 96*4 + 1536
#define NN (Nn*Nn)
#define PROJD 1152  // 192 + 384 + 144 + 432
#define QS 0.14433756729740643f   // sqrt(1/48)

typedef unsigned long long ull;

// ---------------- scratch (device globals; no allocation) ----------------
__device__ float g_proj[Nn*PROJD];
__device__ float g_qpts[Nn*Hh*PQ*3];      // [n][h][p][c]
__device__ ull   g_kT2[Hh*8*Nn];          // [h][dpair][j] = {k[2dp], k[2dp+1]}
__device__ float g_vT[Hh*HD*Nn];          // [h][d][j]
__device__ ull   g_kpT2[Hh*6*Nn];         // [h][epair][j]
__device__ float g_vptsT[Hh*24*Nn];       // [h][p*3+c][j]
__device__ float g_knorm[Hh*Nn];          // [h][j] = sum kp^2
__device__ float g_bias[Hh*NN];           // [h][i][j], pre-scaled by sqrt(1/3)
__device__ float g_att[Hh*NN];
__device__ float g_opt[Nn*Hh*PV*3];
__device__ float g_cat[Nn*CATD];

// ---------------- f32x2 packed helpers ------------------------------------
__device__ __forceinline__ ull pk2(float x, float y) {
    ull r; asm("mov.b64 %0, {%1,%2};" : "=l"(r) : "f"(x), "f"(y)); return r;
}
__device__ __forceinline__ ull dup2(float x) {
    ull r; asm("mov.b64 %0, {%1,%1};" : "=l"(r) : "f"(x)); return r;
}
#define FMA2(c, a, b) asm("fma.rn.f32x2 %0, %1, %2, %0;" : "+l"(c) : "l"(a), "l"(b))
__device__ __forceinline__ void unpk2(ull v, float& lo, float& hi) {
    asm("mov.b64 {%0,%1}, %2;" : "=f"(lo), "=f"(hi) : "l"(v));
}
__device__ __forceinline__ float hadd2(ull v) {
    float lo, hi; unpk2(v, lo, hi); return lo + hi;
}

// ------- GEMM (known-good): BM=64,BN=64,BK=16, 256 thr, 4x4 f32x2 ---------
template<bool PROJ>
__global__ void __launch_bounds__(256)
gemm_kernel(const float* __restrict__ A,
            const float* __restrict__ W0,  const float* __restrict__ b0,
            const float* __restrict__ Wkv, const float* __restrict__ bkv,
            const float* __restrict__ Wqp, const float* __restrict__ bqp,
            const float* __restrict__ Wkvp,const float* __restrict__ bkvp,
            float* __restrict__ C, int Nd, int K) {
    __shared__ __align__(16) ull As2[16][64];   // [k][row] dup pairs {a,a}
    __shared__ __align__(16) ull Bs2[16][32];   // [k][colpair] {b0,b1}
    int tid = threadIdx.x;
    int m0 = blockIdx.y * 64, n0 = blockIdx.x * 64;
    int tx = tid & 15, ty = tid >> 4;

    int arow = tid >> 2, akb = (tid & 3) * 4;
    const float* Aptr = A + (size_t)(m0 + arow) * K + akb;

    int lcol = n0 + tx * 4;
    const float* Bsrc; int ldw; int lc;
    if (PROJ) {
        if      (lcol < 192) { Bsrc = W0;   ldw = 192; lc = lcol;       }
        else if (lcol < 576) { Bsrc = Wkv;  ldw = 384; lc = lcol - 192; }
        else if (lcol < 720) { Bsrc = Wqp;  ldw = 144; lc = lcol - 576; }
        else                 { Bsrc = Wkvp; ldw = 432; lc = lcol - 720; }
    } else { Bsrc = W0; ldw = Nd; lc = lcol; }
    const float* Bptr = Bsrc + (size_t)ty * ldw + lc;

    float4 a4 = *(const float4*)Aptr;
    float4 b4 = *(const float4*)Bptr;

    ull acc[4][2];
    #pragma unroll
    for (int r = 0; r < 4; r++) { acc[r][0] = 0ull; acc[r][1] = 0ull; }

    int KT = K >> 4;
    for (int kt = 0; kt < KT; kt++) {
        __syncthreads();
        As2[akb + 0][arow] = dup2(a4.x);
        As2[akb + 1][arow] = dup2(a4.y);
        As2[akb + 2][arow] = dup2(a4.z);
        As2[akb + 3][arow] = dup2(a4.w);
        Bs2[ty][tx * 2]     = pk2(b4.x, b4.y);
        Bs2[ty][tx * 2 + 1] = pk2(b4.z, b4.w);
        __syncthreads();
        if (kt + 1 < KT) {
            a4 = *(const float4*)(Aptr + (kt + 1) * 16);
            b4 = *(const float4*)(Bptr + (size_t)(kt + 1) * 16 * ldw);
        }
        #pragma unroll
        for (int kk = 0; kk < 16; kk++) {
            ulonglong2 ap0 = *(const ulonglong2*)&As2[kk][ty * 4];
            ulonglong2 ap1 = *(const ulonglong2*)&As2[kk][ty * 4 + 2];
            ulonglong2 bp  = *(const ulonglong2*)&Bs2[kk][tx * 2];
            FMA2(acc[0][0], ap0.x, bp.x); FMA2(acc[0][1], ap0.x, bp.y);
            FMA2(acc[1][0], ap0.y, bp.x); FMA2(acc[1][1], ap0.y, bp.y);
            FMA2(acc[2][0], ap1.x, bp.x); FMA2(acc[2][1], ap1.x, bp.y);
            FMA2(acc[3][0], ap1.y, bp.x); FMA2(acc[3][1], ap1.y, bp.y);
        }
    }
    const float* bsrc; float scale;
    if (PROJ) {
        if      (lcol < 192) { bsrc = b0;   scale = QS; }
        else if (lcol < 576) { bsrc = bkv;  scale = 1.f; }
        else if (lcol < 720) { bsrc = bqp;  scale = 1.f; }
        else                 { bsrc = bkvp; scale = 1.f; }
    } else { bsrc = b0; scale = 1.f; }
    int lcb = PROJ ? ((lcol < 192) ? lcol : (lcol < 576) ? lcol - 192
                       : (lcol < 720) ? lcol - 576 : lcol - 720) : lcol;
    float4 bv = *(const float4*)(bsrc + lcb);
    #pragma unroll
    for (int r = 0; r < 4; r++) {
        float o0, o1, o2, o3;
        unpk2(acc[r][0], o0, o1);
        unpk2(acc[r][1], o2, o3);
        float4 o;
        o.x = (o0 + bv.x) * scale; o.y = (o1 + bv.y) * scale;
        o.z = (o2 + bv.z) * scale; o.w = (o3 + bv.w) * scale;
        *(float4*)(C + (size_t)(m0 + ty * 4 + r) * Nd + n0 + tx * 4) = o;
    }
}

// ------------- merged: point transforms + k/v repack (576 threads) --------
__global__ void __launch_bounds__(576)
pts_kernel(const float* __restrict__ rot,
           const float* __restrict__ trans) {
    int n = blockIdx.x;
    __shared__ float R[9], t3[3];
    __shared__ float kn[Hh][PQ];
    int tid = threadIdx.x;
    if (tid < 9) R[tid] = rot[n * 9 + tid];
    if (tid < 3) t3[tid] = trans[n * 3 + tid];
    __syncthreads();
    if (tid < 48) {
        int idx = tid;
        const float* raw = g_proj + n * PROJD + 576;
        float p0 = raw[idx], p1 = raw[48 + idx], p2 = raw[96 + idx];
        #pragma unroll
        for (int c = 0; c < 3; c++)
            g_qpts[n * 144 + idx * 3 + c] =
                R[c * 3] * p0 + R[c * 3 + 1] * p1 + R[c * 3 + 2] * p2 + t3[c];
    } else if (tid < 192) {
        int idx = tid - 48;
        const float* raw = g_proj + n * PROJD + 720;
        float p0 = raw[idx], p1 = raw[144 + idx], p2 = raw[288 + idx];
        int h = idx / 12, r = idx - h * 12;
        float o[3];
        #pragma unroll
        for (int c = 0; c < 3; c++)
            o[c] = R[c * 3] * p0 + R[c * 3 + 1] * p1 + R[c * 3 + 2] * p2 + t3[c];
        if (r < PQ) {
            float* fp = (float*)g_kpT2;
            #pragma unroll
            for (int c = 0; c < 3; c++) {
                int e = r * 3 + c;
                fp[((h * 6 + (e >> 1)) * Nn + n) * 2 + (e & 1)] = o[c];
            }
            kn[h][r] = o[0] * o[0] + o[1] * o[1] + o[2] * o[2];
        } else {
            int p = r - PQ;
            #pragma unroll
            for (int c = 0; c < 3; c++)
                g_vptsT[(h * 24 + p * 3 + c) * Nn + n] = o[c];
        }
    } else {
        int rt = tid - 192;   // 0..383 = h*32 + d
        float v = g_proj[n * PROJD + 192 + rt];
        int h = rt >> 5, d = rt & 31;
        if (d < 16) {
            float* fk = (float*)g_kT2;
            fk[((h * 8 + (d >> 1)) * Nn + n) * 2 + (d & 1)] = v;
        } else {
            g_vT[(h * 16 + d - 16) * Nn + n] = v;
        }
    }
    __syncthreads();
    if (tid < Hh)
        g_knorm[tid * Nn + n] = kn[tid][0] + kn[tid][1] + kn[tid][2] + kn[tid][3];
}

// ---------- bias: f32x2, double-buffered quarter-staged z -----------------
__global__ void __launch_bounds__(128)
bias_kernel(const float* __restrict__ z,
            const float* __restrict__ Wb,
            const float* __restrict__ bb) {
    int base = blockIdx.x * 128;
    __shared__ __align__(16) ull zs[2][128][17];  // [buf][row][c-pair], native ull
    __shared__ __align__(16) ull WbP[64][Hh];     // [c-pair][h]
    int tid = threadIdx.x;
    for (int t = tid; t < 64 * Hh; t += 128) {
        int cp = t / Hh, h = t - cp * Hh;
        WbP[cp][h] = pk2(Wb[(2 * cp) * Hh + h], Wb[(2 * cp + 1) * Hh + h]);
    }
    ull acc2[Hh];
    #pragma unroll
    for (int h = 0; h < Hh; h++) acc2[h] = 0ull;

    // stage quarter 0 into buffer 0
    #pragma unroll
    for (int u = 0; u < 8; u++) {
        int t = tid + u * 128;
        int row = t >> 3, cc = (t & 7) * 4;
        float4 v = *(const float4*)&z[(size_t)(base + row) * CZ + cc];
        zs[0][row][cc >> 1]       = pk2(v.x, v.y);
        zs[0][row][(cc >> 1) + 1] = pk2(v.z, v.w);
    }
    #pragma unroll
    for (int q = 0; q < 4; q++) {
        __syncthreads();
        if (q < 3) {
            int nb = (q + 1) & 1;
            #pragma unroll
            for (int u = 0; u < 8; u++) {
                int t = tid + u * 128;
                int row = t >> 3, cc = (t & 7) * 4;
                float4 v = *(const float4*)&z[(size_t)(base + row) * CZ + (q + 1) * 32 + cc];
                zs[nb][row][cc >> 1]       = pk2(v.x, v.y);
                zs[nb][row][(cc >> 1) + 1] = pk2(v.z, v.w);
            }
        }
        int cb = q & 1;
        #pragma unroll
        for (int cl = 0; cl < 16; cl++) {
            ull zp = zs[cb][tid][cl];
            const ull* wp = &WbP[q * 16 + cl][0];
            #pragma unroll
            for (int hp = 0; hp < 6; hp++) {
                ulonglong2 w2 = *(const ulonglong2*)(wp + hp * 2);
                FMA2(acc2[2 * hp],     zp, w2.x);
                FMA2(acc2[2 * hp + 1], zp, w2.y);
            }
        }
    }
    int ij = base + tid;
    #pragma unroll
    for (int h = 0; h < Hh; h++)
        g_bias[h * NN + ij] = 0.5773502691896258f * (hadd2(acc2[h]) + bb[h]);
}

// ---------- attention logits + softmax, 8 rows/block, packed K loads ------
__global__ void __launch_bounds__(256)
attn_kernel(const float* __restrict__ head_w,
            const float* __restrict__ mask) {
    int h = blockIdx.x, i0 = blockIdx.y * 8;
    __shared__ __align__(16) float qv[8][16];
    __shared__ __align__(16) float qp[8][12];
    __shared__ float mi8[8], qn8[8];
    __shared__ float red[8][8];
    __shared__ float s_hw, s_res[8];
    int tid = threadIdx.x, lane = tid & 31, wid = tid >> 5;
    if (tid < 128) {
        int ii = tid >> 4, d = tid & 15;
        qv[ii][d] = g_proj[(i0 + ii) * PROJD + h * 16 + d];
    }
    if (tid < 96) {
        int ii = tid / 12, e = tid - ii * 12;
        qp[ii][e] = g_qpts[(i0 + ii) * 144 + h * 12 + e];
    }
    if (tid < 8) mi8[tid] = mask[i0 + tid];
    if (tid == 0) {
        float w = head_w[h];
        float sp = fmaxf(w, 0.f) + log1pf(__expf(-fabsf(w)));
        s_hw = sp * 0.5f * 0.13608276348795434f;   // 0.5*sqrt(1/54)
    }
    __syncthreads();
    if (tid < 8) {
        float s = 0.f;
        #pragma unroll
        for (int e = 0; e < 12; e++) s += qp[tid][e] * qp[tid][e];
        qn8[tid] = s;
    }
    __syncthreads();
    float hw = s_hw, hw2 = 2.f * s_hw;
    float logit[8][2];
    #pragma unroll
    for (int jj = 0; jj < 2; jj++) {
        int j = tid + jj * 256;
        ull kx2[8], kp2[6];
        #pragma unroll
        for (int d = 0; d < 8; d++) kx2[d] = g_kT2[(h * 8 + d) * Nn + j];
        #pragma unroll
        for (int e = 0; e < 6; e++) kp2[e] = g_kpT2[(h * 6 + e) * Nn + j];
        float kn = g_knorm[h * Nn + j];
        float mj = mask[j];
        #pragma unroll
        for (int ii = 0; ii < 8; ii++) {
            ull dk = 0ull, dp = 0ull;
            const ull* q2 = (const ull*)&qv[ii][0];
            const ull* p2 = (const ull*)&qp[ii][0];
            #pragma unroll
            for (int d = 0; d < 8; d++) FMA2(dk, q2[d], kx2[d]);
            #pragma unroll
            for (int e = 0; e < 6; e++) FMA2(dp, p2[e], kp2[e]);
            float dot = hadd2(dk), dpt = hadd2(dp);
            logit[ii][jj] = dot + g_bias[(h << 18) + ((i0 + ii) << 9) + j]
                          - hw * (qn8[ii] + kn) + hw2 * dpt
                          + 100000.0f * (mi8[ii] * mj - 1.0f);
        }
    }
    #pragma unroll
    for (int ii = 0; ii < 8; ii++) {
        float m = fmaxf(logit[ii][0], logit[ii][1]);
        #pragma unroll
        for (int o = 16; o > 0; o >>= 1) m = fmaxf(m, __shfl_xor_sync(0xffffffffu, m, o));
        if (lane == 0) red[ii][wid] = m;
    }
    __syncthreads();
    if (tid < 8) {
        float mm = red[tid][0];
        #pragma unroll
        for (int w = 1; w < 8; w++) mm = fmaxf(mm, red[tid][w]);
        s_res[tid] = mm;
    }
    __syncthreads();
    #pragma unroll
    for (int ii = 0; ii < 8; ii++) {
        float m = s_res[ii];
        logit[ii][0] = __expf(logit[ii][0] - m);
        logit[ii][1] = __expf(logit[ii][1] - m);
        float ss = logit[ii][0] + logit[ii][1];
        #pragma unroll
        for (int o = 16; o > 0; o >>= 1) ss += __shfl_xor_sync(0xffffffffu, ss, o);
        if (lane == 0) red[ii][wid] = ss;
    }
    __syncthreads();
    if (tid < 8) {
        float t = 0.f;
        #pragma unroll
        for (int w = 0; w < 8; w++) t += red[tid][w];
        s_res[tid] = 1.f / t;
    }
    __syncthreads();
    #pragma unroll
    for (int ii = 0; ii < 8; ii++) {
        float inv = s_res[ii];
        int o = (h << 18) + ((i0 + ii) << 9);
        g_att[o + tid]       = logit[ii][0] * inv;
        g_att[o + tid + 256] = logit[ii][1] * inv;
    }
}

// ---------- a@[v | v_pts] per head, 32-row tiles, coalesced loads ---------
__global__ void __launch_bounds__(320)
av_kernel() {
    int h = blockIdx.x;
    int i0 = blockIdx.y * 32;
    __shared__ __align__(16) float As[32][36];
    __shared__ __align__(16) float Vt[32][40];
    int tid = threadIdx.x;
    int tx = tid % 40, ty = tid / 40;
    float acc[4] = {};
    for (int k0 = 0; k0 < Nn; k0 += 32) {
        __syncthreads();
        for (int t = tid; t < 1024; t += 320) {
            int j = t & 31, ii = t >> 5;
            As[j][ii] = g_att[(h << 18) + ((i0 + ii) << 9) + k0 + j];
        }
        for (int t = tid; t < 1280; t += 320) {
            int col = t >> 5, row = t & 31;
            Vt[row][col] = (col < 16)
                ? g_vT[(h * 16 + col) * Nn + k0 + row]
                : g_vptsT[(h * 24 + col - 16) * Nn + k0 + row];
        }
        __syncthreads();
        #pragma unroll
        for (int j = 0; j < 32; j++) {
            float b = Vt[j][tx];
            float4 a = *(const float4*)&As[j][ty * 4];
            acc[0] += a.x * b; acc[1] += a.y * b;
            acc[2] += a.z * b; acc[3] += a.w * b;
        }
    }
    #pragma unroll
    for (int r = 0; r < 4; r++) {
        int i = i0 + ty * 4 + r;
        if (tx < 16) g_cat[(size_t)i * CATD + h * 16 + tx] = acc[r];
        else         g_opt[i * 288 + h * 24 + (tx - 16)]   = acc[r];
    }
}

// ---------- inverse frame transform + norm -> cat sections ----------------
__global__ void transform_kernel(const float* __restrict__ rot,
                                 const float* __restrict__ trans) {
    int n = blockIdx.x;
    __shared__ float R[9], t3[3];
    int tid = threadIdx.x;   // 128
    if (tid < 9) R[tid] = rot[n * 9 + tid];
    if (tid < 3) t3[tid] = trans[n * 3 + tid];
    __syncthreads();
    if (tid < 96) {
        int h = tid >> 3, p = tid & 7;
        int base = n * 288 + h * 24 + p * 3;
        float x = g_opt[base + 0] - t3[0];
        float y = g_opt[base + 1] - t3[1];
        float z = g_opt[base + 2] - t3[2];
        float lx = R[0] * x + R[3] * y + R[6] * z;
        float ly = R[1] * x + R[4] * y + R[7] * z;
        float lz = R[2] * x + R[5] * y + R[8] * z;
        size_t o = (size_t)n * CATD;
        int idx = h * 8 + p;
        g_cat[o + 192 + idx] = lx;
        g_cat[o + 288 + idx] = ly;
        g_cat[o + 384 + idx] = lz;
        g_cat[o + 480 + idx] = sqrtf(lx * lx + ly * ly + lz * lz + 1e-8f);
    }
}

// ---------- o_pair: f32x2 over j-pairs, MLP-8 z loads ---------------------
__global__ void __launch_bounds__(512)
opair_kernel(const float* __restrict__ z) {
    int i = blockIdx.x;
    __shared__ __align__(16) float as[Hh][520];
    int tid = threadIdx.x;
    int c = tid & 127, jq = tid >> 7;
    for (int t = tid; t < Hh * Nn; t += 512) {
        int h = t >> 9, j = t & 511;
        as[h][j] = g_att[(h << 18) + (i << 9) + j];
    }
    __syncthreads();
    ull acc2[Hh];
    #pragma unroll
    for (int h = 0; h < Hh; h++) acc2[h] = 0ull;
    const float* zrow = z + (size_t)i * Nn * CZ + c;
    int j0 = jq * 128;
    for (int j = j0; j < j0 + 128; j += 8) {
        float zr[8];
        #pragma unroll
        for (int u = 0; u < 8; u++) zr[u] = zrow[(size_t)(j + u) * CZ];
        ull zp0 = pk2(zr[0], zr[1]), zp1 = pk2(zr[2], zr[3]);
        ull zp2 = pk2(zr[4], zr[5]), zp3 = pk2(zr[6], zr[7]);
        #pragma unroll
        for (int h = 0; h < Hh; h++) {
            ulonglong2 a0 = *(const ulonglong2*)&as[h][j];      // 16-aligned (j%8==0)
            ulonglong2 a1 = *(const ulonglong2*)&as[h][j + 4];
            FMA2(acc2[h], a0.x, zp0);
            FMA2(acc2[h], a0.y, zp1);
            FMA2(acc2[h], a1.x, zp2);
            FMA2(acc2[h], a1.y, zp3);
        }
    }
    __syncthreads();
    float* red = &as[0][0];
    if (jq > 0) {
        #pragma unroll
        for (int h = 0; h < Hh; h++)
            red[(jq - 1) * 1536 + h * 128 + c] = hadd2(acc2[h]);
    }
    __syncthreads();
    if (jq == 0) {
        size_t o = (size_t)i * CATD + 576;
        #pragma unroll
        for (int h = 0; h < Hh; h++) {
            float v = hadd2(acc2[h]) + red[h * 128 + c] + red[1536 + h * 128 + c]
                             + red[3072 + h * 128 + c];
            g_cat[o + h * CZ + c] = v;
        }
    }
}

// --------------------------------------------------------------------------
extern "C" void kernel_launch(void* const* d_in, const int* in_sizes, int n_in,
                              void* d_out, int out_size) {
    const float* s      = (const float*)d_in[0];
    const float* z      = (const float*)d_in[1];
    const float* rot    = (const float*)d_in[2];
    const float* trans  = (const float*)d_in[3];
    const float* mask   = (const float*)d_in[4];
    const float* Wq     = (const float*)d_in[5];
    const float* bq     = (const float*)d_in[6];
    const float* Wkv    = (const float*)d_in[7];
    const float* bkv    = (const float*)d_in[8];
    const float* Wqp    = (const float*)d_in[9];
    const float* bqp    = (const float*)d_in[10];
    const float* Wkvp   = (const float*)d_in[11];
    const float* bkvp   = (const float*)d_in[12];
    const float* Wb     = (const float*)d_in[13];
    const float* bb     = (const float*)d_in[14];
    const float* head_w = (const float*)d_in[15];
    const float* Wout   = (const float*)d_in[16];
    const float* bout   = (const float*)d_in[17];
    float* out = (float*)d_out;

    float *p_proj, *p_cat;
    cudaGetSymbolAddress((void**)&p_proj, g_proj);
    cudaGetSymbolAddress((void**)&p_cat,  g_cat);

    gemm_kernel<true><<<dim3(PROJD / 64, Nn / 64), 256>>>(
        s, Wq, bq, Wkv, bkv, Wqp, bqp, Wkvp, bkvp, p_proj, PROJD, CS);
    pts_kernel<<<Nn, 576>>>(rot, trans);
    bias_kernel<<<NN / 128, 128>>>(z, Wb, bb);
    attn_kernel<<<dim3(Hh, Nn / 8), 256>>>(head_w, mask);
    av_kernel<<<dim3(Hh, Nn / 32), 320>>>();
    transform_kernel<<<Nn, 128>>>(rot, trans);
    opair_kernel<<<Nn, 512>>>(z);
    gemm_kernel<false><<<dim3(CS / 64, Nn / 64), 256>>>(
        p_cat, Wout, bout, 0, 0, 0, 0, 0, 0, out, CS, CATD);
}

// round 12
// speedup vs baseline: 1.1886x; 1.0178x over previous
#include <cuda_runtime.h>
#include <math.h>

#define Nn 512
#define CS 1024
#define CZ 128
#define Hh 12
#define HD 16
#define PQ 4
#define PV 8
#define CATD 2112   // 192 + 96*4 + 1536
#define NN (Nn*Nn)
#define PROJD 1152  // 192 + 384 + 144 + 432
#define QS 0.14433756729740643f   // sqrt(1/48)

typedef unsigned long long ull;

// ---------------- scratch (device globals; no allocation) ----------------
__device__ float g_proj[Nn*PROJD];
__device__ float g_qpts[Nn*Hh*PQ*3];      // [n][h][p][c]
__device__ ull   g_kT2[Hh*8*Nn];          // [h][dpair][j] = {k[2dp], k[2dp+1]}
__device__ float g_vT[Hh*HD*Nn];          // [h][d][j]
__device__ ull   g_kpT2[Hh*6*Nn];         // [h][epair][j]
__device__ float g_vptsT[Hh*24*Nn];       // [h][p*3+c][j]
__device__ float g_knorm[Hh*Nn];          // [h][j] = sum kp^2
__device__ float g_bias[Hh*NN];           // [h][i][j], pre-scaled by sqrt(1/3)
__device__ float g_att[Hh*NN];
__device__ float g_opt[Nn*Hh*PV*3];
__device__ float g_cat[Nn*CATD];

// ---------------- f32x2 packed helpers ------------------------------------
__device__ __forceinline__ ull pk2(float x, float y) {
    ull r; asm("mov.b64 %0, {%1,%2};" : "=l"(r) : "f"(x), "f"(y)); return r;
}
__device__ __forceinline__ ull dup2(float x) {
    ull r; asm("mov.b64 %0, {%1,%1};" : "=l"(r) : "f"(x)); return r;
}
#define FMA2(c, a, b) asm("fma.rn.f32x2 %0, %1, %2, %0;" : "+l"(c) : "l"(a), "l"(b))
__device__ __forceinline__ void unpk2(ull v, float& lo, float& hi) {
    asm("mov.b64 {%0,%1}, %2;" : "=f"(lo), "=f"(hi) : "l"(v));
}
__device__ __forceinline__ float hadd2(ull v) {
    float lo, hi; unpk2(v, lo, hi); return lo + hi;
}

// ------- GEMM (known-good): BM=64,BN=64,BK=16, 256 thr, 4x4 f32x2 ---------
template<bool PROJ>
__global__ void __launch_bounds__(256)
gemm_kernel(const float* __restrict__ A,
            const float* __restrict__ W0,  const float* __restrict__ b0,
            const float* __restrict__ Wkv, const float* __restrict__ bkv,
            const float* __restrict__ Wqp, const float* __restrict__ bqp,
            const float* __restrict__ Wkvp,const float* __restrict__ bkvp,
            float* __restrict__ C, int Nd, int K) {
    __shared__ __align__(16) ull As2[16][64];   // [k][row] dup pairs {a,a}
    __shared__ __align__(16) ull Bs2[16][32];   // [k][colpair] {b0,b1}
    int tid = threadIdx.x;
    int m0 = blockIdx.y * 64, n0 = blockIdx.x * 64;
    int tx = tid & 15, ty = tid >> 4;

    int arow = tid >> 2, akb = (tid & 3) * 4;
    const float* Aptr = A + (size_t)(m0 + arow) * K + akb;

    int lcol = n0 + tx * 4;
    const float* Bsrc; int ldw; int lc;
    if (PROJ) {
        if      (lcol < 192) { Bsrc = W0;   ldw = 192; lc = lcol;       }
        else if (lcol < 576) { Bsrc = Wkv;  ldw = 384; lc = lcol - 192; }
        else if (lcol < 720) { Bsrc = Wqp;  ldw = 144; lc = lcol - 576; }
        else                 { Bsrc = Wkvp; ldw = 432; lc = lcol - 720; }
    } else { Bsrc = W0; ldw = Nd; lc = lcol; }
    const float* Bptr = Bsrc + (size_t)ty * ldw + lc;

    float4 a4 = *(const float4*)Aptr;
    float4 b4 = *(const float4*)Bptr;

    ull acc[4][2];
    #pragma unroll
    for (int r = 0; r < 4; r++) { acc[r][0] = 0ull; acc[r][1] = 0ull; }

    int KT = K >> 4;
    for (int kt = 0; kt < KT; kt++) {
        __syncthreads();
        As2[akb + 0][arow] = dup2(a4.x);
        As2[akb + 1][arow] = dup2(a4.y);
        As2[akb + 2][arow] = dup2(a4.z);
        As2[akb + 3][arow] = dup2(a4.w);
        Bs2[ty][tx * 2]     = pk2(b4.x, b4.y);
        Bs2[ty][tx * 2 + 1] = pk2(b4.z, b4.w);
        __syncthreads();
        if (kt + 1 < KT) {
            a4 = *(const float4*)(Aptr + (kt + 1) * 16);
            b4 = *(const float4*)(Bptr + (size_t)(kt + 1) * 16 * ldw);
        }
        #pragma unroll
        for (int kk = 0; kk < 16; kk++) {
            ulonglong2 ap0 = *(const ulonglong2*)&As2[kk][ty * 4];
            ulonglong2 ap1 = *(const ulonglong2*)&As2[kk][ty * 4 + 2];
            ulonglong2 bp  = *(const ulonglong2*)&Bs2[kk][tx * 2];
            FMA2(acc[0][0], ap0.x, bp.x); FMA2(acc[0][1], ap0.x, bp.y);
            FMA2(acc[1][0], ap0.y, bp.x); FMA2(acc[1][1], ap0.y, bp.y);
            FMA2(acc[2][0], ap1.x, bp.x); FMA2(acc[2][1], ap1.x, bp.y);
            FMA2(acc[3][0], ap1.y, bp.x); FMA2(acc[3][1], ap1.y, bp.y);
        }
    }
    const float* bsrc; float scale;
    if (PROJ) {
        if      (lcol < 192) { bsrc = b0;   scale = QS; }
        else if (lcol < 576) { bsrc = bkv;  scale = 1.f; }
        else if (lcol < 720) { bsrc = bqp;  scale = 1.f; }
        else                 { bsrc = bkvp; scale = 1.f; }
    } else { bsrc = b0; scale = 1.f; }
    int lcb = PROJ ? ((lcol < 192) ? lcol : (lcol < 576) ? lcol - 192
                       : (lcol < 720) ? lcol - 576 : lcol - 720) : lcol;
    float4 bv = *(const float4*)(bsrc + lcb);
    #pragma unroll
    for (int r = 0; r < 4; r++) {
        float o0, o1, o2, o3;
        unpk2(acc[r][0], o0, o1);
        unpk2(acc[r][1], o2, o3);
        float4 o;
        o.x = (o0 + bv.x) * scale; o.y = (o1 + bv.y) * scale;
        o.z = (o2 + bv.z) * scale; o.w = (o3 + bv.w) * scale;
        *(float4*)(C + (size_t)(m0 + ty * 4 + r) * Nd + n0 + tx * 4) = o;
    }
}

// ------------- merged: point transforms + k/v repack (576 threads) --------
__global__ void __launch_bounds__(576)
pts_kernel(const float* __restrict__ rot,
           const float* __restrict__ trans) {
    int n = blockIdx.x;
    __shared__ float R[9], t3[3];
    __shared__ float kn[Hh][PQ];
    int tid = threadIdx.x;
    if (tid < 9) R[tid] = rot[n * 9 + tid];
    if (tid < 3) t3[tid] = trans[n * 3 + tid];
    __syncthreads();
    if (tid < 48) {
        int idx = tid;
        const float* raw = g_proj + n * PROJD + 576;
        float p0 = raw[idx], p1 = raw[48 + idx], p2 = raw[96 + idx];
        #pragma unroll
        for (int c = 0; c < 3; c++)
            g_qpts[n * 144 + idx * 3 + c] =
                R[c * 3] * p0 + R[c * 3 + 1] * p1 + R[c * 3 + 2] * p2 + t3[c];
    } else if (tid < 192) {
        int idx = tid - 48;
        const float* raw = g_proj + n * PROJD + 720;
        float p0 = raw[idx], p1 = raw[144 + idx], p2 = raw[288 + idx];
        int h = idx / 12, r = idx - h * 12;
        float o[3];
        #pragma unroll
        for (int c = 0; c < 3; c++)
            o[c] = R[c * 3] * p0 + R[c * 3 + 1] * p1 + R[c * 3 + 2] * p2 + t3[c];
        if (r < PQ) {
            float* fp = (float*)g_kpT2;
            #pragma unroll
            for (int c = 0; c < 3; c++) {
                int e = r * 3 + c;
                fp[((h * 6 + (e >> 1)) * Nn + n) * 2 + (e & 1)] = o[c];
            }
            kn[h][r] = o[0] * o[0] + o[1] * o[1] + o[2] * o[2];
        } else {
            int p = r - PQ;
            #pragma unroll
            for (int c = 0; c < 3; c++)
                g_vptsT[(h * 24 + p * 3 + c) * Nn + n] = o[c];
        }
    } else {
        int rt = tid - 192;   // 0..383 = h*32 + d
        float v = g_proj[n * PROJD + 192 + rt];
        int h = rt >> 5, d = rt & 31;
        if (d < 16) {
            float* fk = (float*)g_kT2;
            fk[((h * 8 + (d >> 1)) * Nn + n) * 2 + (d & 1)] = v;
        } else {
            g_vT[(h * 16 + d - 16) * Nn + n] = v;
        }
    }
    __syncthreads();
    if (tid < Hh)
        g_knorm[tid * Nn + n] = kn[tid][0] + kn[tid][1] + kn[tid][2] + kn[tid][3];
}

// ---------- bias: f32x2, double-buffered quarter-staged z -----------------
__global__ void __launch_bounds__(128)
bias_kernel(const float* __restrict__ z,
            const float* __restrict__ Wb,
            const float* __restrict__ bb) {
    int base = blockIdx.x * 128;
    __shared__ __align__(16) ull zs[2][128][17];  // [buf][row][c-pair], native ull
    __shared__ __align__(16) ull WbP[64][Hh];     // [c-pair][h]
    int tid = threadIdx.x;
    for (int t = tid; t < 64 * Hh; t += 128) {
        int cp = t / Hh, h = t - cp * Hh;
        WbP[cp][h] = pk2(Wb[(2 * cp) * Hh + h], Wb[(2 * cp + 1) * Hh + h]);
    }
    ull acc2[Hh];
    #pragma unroll
    for (int h = 0; h < Hh; h++) acc2[h] = 0ull;

    #pragma unroll
    for (int u = 0; u < 8; u++) {
        int t = tid + u * 128;
        int row = t >> 3, cc = (t & 7) * 4;
        float4 v = *(const float4*)&z[(size_t)(base + row) * CZ + cc];
        zs[0][row][cc >> 1]       = pk2(v.x, v.y);
        zs[0][row][(cc >> 1) + 1] = pk2(v.z, v.w);
    }
    #pragma unroll
    for (int q = 0; q < 4; q++) {
        __syncthreads();
        if (q < 3) {
            int nb = (q + 1) & 1;
            #pragma unroll
            for (int u = 0; u < 8; u++) {
                int t = tid + u * 128;
                int row = t >> 3, cc = (t & 7) * 4;
                float4 v = *(const float4*)&z[(size_t)(base + row) * CZ + (q + 1) * 32 + cc];
                zs[nb][row][cc >> 1]       = pk2(v.x, v.y);
                zs[nb][row][(cc >> 1) + 1] = pk2(v.z, v.w);
            }
        }
        int cb = q & 1;
        #pragma unroll
        for (int cl = 0; cl < 16; cl++) {
            ull zp = zs[cb][tid][cl];
            const ull* wp = &WbP[q * 16 + cl][0];
            #pragma unroll
            for (int hp = 0; hp < 6; hp++) {
                ulonglong2 w2 = *(const ulonglong2*)(wp + hp * 2);
                FMA2(acc2[2 * hp],     zp, w2.x);
                FMA2(acc2[2 * hp + 1], zp, w2.y);
            }
        }
    }
    int ij = base + tid;
    #pragma unroll
    for (int h = 0; h < Hh; h++)
        g_bias[h * NN + ij] = 0.5773502691896258f * (hadd2(acc2[h]) + bb[h]);
}

// ---------- attention logits + softmax, 8 rows/block, packed K loads ------
__global__ void __launch_bounds__(256)
attn_kernel(const float* __restrict__ head_w,
            const float* __restrict__ mask) {
    int h = blockIdx.x, i0 = blockIdx.y * 8;
    __shared__ __align__(16) float qv[8][16];
    __shared__ __align__(16) float qp[8][12];
    __shared__ float mi8[8], qn8[8];
    __shared__ float red[8][8];
    __shared__ float s_hw, s_res[8];
    int tid = threadIdx.x, lane = tid & 31, wid = tid >> 5;
    if (tid < 128) {
        int ii = tid >> 4, d = tid & 15;
        qv[ii][d] = g_proj[(i0 + ii) * PROJD + h * 16 + d];
    }
    if (tid < 96) {
        int ii = tid / 12, e = tid - ii * 12;
        qp[ii][e] = g_qpts[(i0 + ii) * 144 + h * 12 + e];
    }
    if (tid < 8) mi8[tid] = mask[i0 + tid];
    if (tid == 0) {
        float w = head_w[h];
        float sp = fmaxf(w, 0.f) + log1pf(__expf(-fabsf(w)));
        s_hw = sp * 0.5f * 0.13608276348795434f;   // 0.5*sqrt(1/54)
    }
    __syncthreads();
    if (tid < 8) {
        float s = 0.f;
        #pragma unroll
        for (int e = 0; e < 12; e++) s += qp[tid][e] * qp[tid][e];
        qn8[tid] = s;
    }
    __syncthreads();
    float hw = s_hw, hw2 = 2.f * s_hw;
    float logit[8][2];
    #pragma unroll
    for (int jj = 0; jj < 2; jj++) {
        int j = tid + jj * 256;
        ull kx2[8], kp2[6];
        #pragma unroll
        for (int d = 0; d < 8; d++) kx2[d] = g_kT2[(h * 8 + d) * Nn + j];
        #pragma unroll
        for (int e = 0; e < 6; e++) kp2[e] = g_kpT2[(h * 6 + e) * Nn + j];
        float kn = g_knorm[h * Nn + j];
        float mj = mask[j];
        #pragma unroll
        for (int ii = 0; ii < 8; ii++) {
            ull dk = 0ull, dp = 0ull;
            const ull* q2 = (const ull*)&qv[ii][0];
            const ull* p2 = (const ull*)&qp[ii][0];
            #pragma unroll
            for (int d = 0; d < 8; d++) FMA2(dk, q2[d], kx2[d]);
            #pragma unroll
            for (int e = 0; e < 6; e++) FMA2(dp, p2[e], kp2[e]);
            float dot = hadd2(dk), dpt = hadd2(dp);
            logit[ii][jj] = dot + g_bias[(h << 18) + ((i0 + ii) << 9) + j]
                          - hw * (qn8[ii] + kn) + hw2 * dpt
                          + 100000.0f * (mi8[ii] * mj - 1.0f);
        }
    }
    #pragma unroll
    for (int ii = 0; ii < 8; ii++) {
        float m = fmaxf(logit[ii][0], logit[ii][1]);
        #pragma unroll
        for (int o = 16; o > 0; o >>= 1) m = fmaxf(m, __shfl_xor_sync(0xffffffffu, m, o));
        if (lane == 0) red[ii][wid] = m;
    }
    __syncthreads();
    if (tid < 8) {
        float mm = red[tid][0];
        #pragma unroll
        for (int w = 1; w < 8; w++) mm = fmaxf(mm, red[tid][w]);
        s_res[tid] = mm;
    }
    __syncthreads();
    #pragma unroll
    for (int ii = 0; ii < 8; ii++) {
        float m = s_res[ii];
        logit[ii][0] = __expf(logit[ii][0] - m);
        logit[ii][1] = __expf(logit[ii][1] - m);
        float ss = logit[ii][0] + logit[ii][1];
        #pragma unroll
        for (int o = 16; o > 0; o >>= 1) ss += __shfl_xor_sync(0xffffffffu, ss, o);
        if (lane == 0) red[ii][wid] = ss;
    }
    __syncthreads();
    if (tid < 8) {
        float t = 0.f;
        #pragma unroll
        for (int w = 0; w < 8; w++) t += red[tid][w];
        s_res[tid] = 1.f / t;
    }
    __syncthreads();
    #pragma unroll
    for (int ii = 0; ii < 8; ii++) {
        float inv = s_res[ii];
        int o = (h << 18) + ((i0 + ii) << 9);
        g_att[o + tid]       = logit[ii][0] * inv;
        g_att[o + tid + 256] = logit[ii][1] * inv;
    }
}

// ---------- a@[v | v_pts] per head, 32-row tiles, coalesced loads ---------
__global__ void __launch_bounds__(320)
av_kernel() {
    int h = blockIdx.x;
    int i0 = blockIdx.y * 32;
    __shared__ __align__(16) float As[32][36];
    __shared__ __align__(16) float Vt[32][40];
    int tid = threadIdx.x;
    int tx = tid % 40, ty = tid / 40;
    float acc[4] = {};
    for (int k0 = 0; k0 < Nn; k0 += 32) {
        __syncthreads();
        for (int t = tid; t < 1024; t += 320) {
            int j = t & 31, ii = t >> 5;
            As[j][ii] = g_att[(h << 18) + ((i0 + ii) << 9) + k0 + j];
        }
        for (int t = tid; t < 1280; t += 320) {
            int col = t >> 5, row = t & 31;
            Vt[row][col] = (col < 16)
                ? g_vT[(h * 16 + col) * Nn + k0 + row]
                : g_vptsT[(h * 24 + col - 16) * Nn + k0 + row];
        }
        __syncthreads();
        #pragma unroll
        for (int j = 0; j < 32; j++) {
            float b = Vt[j][tx];
            float4 a = *(const float4*)&As[j][ty * 4];
            acc[0] += a.x * b; acc[1] += a.y * b;
            acc[2] += a.z * b; acc[3] += a.w * b;
        }
    }
    #pragma unroll
    for (int r = 0; r < 4; r++) {
        int i = i0 + ty * 4 + r;
        if (tx < 16) g_cat[(size_t)i * CATD + h * 16 + tx] = acc[r];
        else         g_opt[i * 288 + h * 24 + (tx - 16)]   = acc[r];
    }
}

// ---------- inverse frame transform + norm -> cat sections ----------------
__global__ void transform_kernel(const float* __restrict__ rot,
                                 const float* __restrict__ trans) {
    int n = blockIdx.x;
    __shared__ float R[9], t3[3];
    int tid = threadIdx.x;   // 128
    if (tid < 9) R[tid] = rot[n * 9 + tid];
    if (tid < 3) t3[tid] = trans[n * 3 + tid];
    __syncthreads();
    if (tid < 96) {
        int h = tid >> 3, p = tid & 7;
        int base = n * 288 + h * 24 + p * 3;
        float x = g_opt[base + 0] - t3[0];
        float y = g_opt[base + 1] - t3[1];
        float z = g_opt[base + 2] - t3[2];
        float lx = R[0] * x + R[3] * y + R[6] * z;
        float ly = R[1] * x + R[4] * y + R[7] * z;
        float lz = R[2] * x + R[5] * y + R[8] * z;
        size_t o = (size_t)n * CATD;
        int idx = h * 8 + p;
        g_cat[o + 192 + idx] = lx;
        g_cat[o + 288 + idx] = ly;
        g_cat[o + 384 + idx] = lz;
        g_cat[o + 480 + idx] = sqrtf(lx * lx + ly * ly + lz * lz + 1e-8f);
    }
}

// ---------- o_pair: f32x2 over j-pairs, MLP-8 z loads ---------------------
__global__ void __launch_bounds__(512)
opair_kernel(const float* __restrict__ z) {
    int i = blockIdx.x;
    __shared__ __align__(16) float as[Hh][520];
    int tid = threadIdx.x;
    int c = tid & 127, jq = tid >> 7;
    for (int t = tid; t < Hh * Nn; t += 512) {
        int h = t >> 9, j = t & 511;
        as[h][j] = g_att[(h << 18) + (i << 9) + j];
    }
    __syncthreads();
    ull acc2[Hh];
    #pragma unroll
    for (int h = 0; h < Hh; h++) acc2[h] = 0ull;
    const float* zrow = z + (size_t)i * Nn * CZ + c;
    int j0 = jq * 128;
    for (int j = j0; j < j0 + 128; j += 8) {
        float zr[8];
        #pragma unroll
        for (int u = 0; u < 8; u++) zr[u] = zrow[(size_t)(j + u) * CZ];
        ull zp0 = pk2(zr[0], zr[1]), zp1 = pk2(zr[2], zr[3]);
        ull zp2 = pk2(zr[4], zr[5]), zp3 = pk2(zr[6], zr[7]);
        #pragma unroll
        for (int h = 0; h < Hh; h++) {
            ulonglong2 a0 = *(const ulonglong2*)&as[h][j];      // 16-aligned (j%8==0)
            ulonglong2 a1 = *(const ulonglong2*)&as[h][j + 4];
            FMA2(acc2[h], a0.x, zp0);
            FMA2(acc2[h], a0.y, zp1);
            FMA2(acc2[h], a1.x, zp2);
            FMA2(acc2[h], a1.y, zp3);
        }
    }
    __syncthreads();
    float* red = &as[0][0];
    if (jq > 0) {
        #pragma unroll
        for (int h = 0; h < Hh; h++)
            red[(jq - 1) * 1536 + h * 128 + c] = hadd2(acc2[h]);
    }
    __syncthreads();
    if (jq == 0) {
        size_t o = (size_t)i * CATD + 576;
        #pragma unroll
        for (int h = 0; h < Hh; h++) {
            float v = hadd2(acc2[h]) + red[h * 128 + c] + red[1536 + h * 128 + c]
                             + red[3072 + h * 128 + c];
            g_cat[o + h * CZ + c] = v;
        }
    }
}

// --------------------------------------------------------------------------
extern "C" void kernel_launch(void* const* d_in, const int* in_sizes, int n_in,
                              void* d_out, int out_size) {
    const float* s      = (const float*)d_in[0];
    const float* z      = (const float*)d_in[1];
    const float* rot    = (const float*)d_in[2];
    const float* trans  = (const float*)d_in[3];
    const float* mask   = (const float*)d_in[4];
    const float* Wq     = (const float*)d_in[5];
    const float* bq     = (const float*)d_in[6];
    const float* Wkv    = (const float*)d_in[7];
    const float* bkv    = (const float*)d_in[8];
    const float* Wqp    = (const float*)d_in[9];
    const float* bqp    = (const float*)d_in[10];
    const float* Wkvp   = (const float*)d_in[11];
    const float* bkvp   = (const float*)d_in[12];
    const float* Wb     = (const float*)d_in[13];
    const float* bb     = (const float*)d_in[14];
    const float* head_w = (const float*)d_in[15];
    const float* Wout   = (const float*)d_in[16];
    const float* bout   = (const float*)d_in[17];
    float* out = (float*)d_out;

    float *p_proj, *p_cat;
    cudaGetSymbolAddress((void**)&p_proj, g_proj);
    cudaGetSymbolAddress((void**)&p_cat,  g_cat);

    // Fork-join overlap: bias and opair (the two independent z-passes) run
    // on a non-blocking side stream; everything else stays on the main stream.
    cudaStream_t sB;
    cudaStreamCreateWithFlags(&sB, cudaStreamNonBlocking);
    cudaEvent_t evFork, evBias, evAttn, evOpair;
    cudaEventCreateWithFlags(&evFork,  cudaEventDisableTiming);
    cudaEventCreateWithFlags(&evBias,  cudaEventDisableTiming);
    cudaEventCreateWithFlags(&evAttn,  cudaEventDisableTiming);
    cudaEventCreateWithFlags(&evOpair, cudaEventDisableTiming);

    // fork: bias depends only on inputs
    cudaEventRecord(evFork, 0);
    cudaStreamWaitEvent(sB, evFork, 0);
    bias_kernel<<<NN / 128, 128, 0, sB>>>(z, Wb, bb);
    cudaEventRecord(evBias, sB);

    // main chain
    gemm_kernel<true><<<dim3(PROJD / 64, Nn / 64), 256>>>(
        s, Wq, bq, Wkv, bkv, Wqp, bqp, Wkvp, bkvp, p_proj, PROJD, CS);
    pts_kernel<<<Nn, 576>>>(rot, trans);
    cudaStreamWaitEvent(0, evBias, 0);          // join bias before attn
    attn_kernel<<<dim3(Hh, Nn / 8), 256>>>(head_w, mask);

    // fork: opair depends only on attn (+ z input)
    cudaEventRecord(evAttn, 0);
    cudaStreamWaitEvent(sB, evAttn, 0);
    opair_kernel<<<Nn, 512, 0, sB>>>(z);
    cudaEventRecord(evOpair, sB);

    av_kernel<<<dim3(Hh, Nn / 32), 320>>>();
    transform_kernel<<<Nn, 128>>>(rot, trans);
    cudaStreamWaitEvent(0, evOpair, 0);         // join opair before Wout
    gemm_kernel<false><<<dim3(CS / 64, Nn / 64), 256>>>(
        p_cat, Wout, bout, 0, 0, 0, 0, 0, 0, out, CS, CATD);

    cudaEventDestroy(evFork);
    cudaEventDestroy(evBias);
    cudaEventDestroy(evAttn);
    cudaEventDestroy(evOpair);
    cudaStreamDestroy(sB);
}